// round 7
// baseline (speedup 1.0000x reference)
#include <cuda_runtime.h>

#define NBLK 64
#define TPB  288          // 9 warps: 8 MLP-row warps + 1 SEIR warp
#define WID  1024
#define HID  256
#define NST  17
#define NY   273          // 17 + 256
#define XPAD 288
#define RH   16           // hidden rows per block
#define RPW  2            // rows per warp (hidden)
#define RL   4            // output rows per block
#define T_N  64
#define SUB  8
#define NHID 3

// ---------------- global scratch (no allocs allowed) ----------------
__device__ __align__(16) float g_z[2][WID];   // double-buffered layer activations
__device__ float g_k[2][4][NY];               // RK4 slopes, parity-buffered
__device__ unsigned g_cnt;                    // arrival counter (reset each launch)

// ---------------- shared memory layout (floats) ----------------
#define OFF_WH   0
#define OFF_WL   (OFF_WH + NHID*RH*WID)    // 49152
#define OFF_Z    (OFF_WL + RL*WID)         // 53248
#define OFF_X    (OFF_Z + WID)             // 54272
#define OFF_B0   (OFF_X + XPAD)
#define OFF_BH   (OFF_B0 + RH)
#define OFF_BL   (OFF_BH + NHID*RH)
#define OFF_BB   (OFF_BL + RL)
#define OFF_BW   (OFF_BB + 1)
#define SMEM_FLOATS (OFF_BW + HID)
#define SMEM_BYTES  (SMEM_FLOATS * 4)      // ~219.6 KB

__device__ __forceinline__ unsigned ld_acq(unsigned* p) {
    unsigned v;
    asm volatile("ld.acquire.gpu.global.u32 %0, [%1];" : "=r"(v) : "l"(p) : "memory");
    return v;
}
__device__ __forceinline__ void red_rel_add(unsigned* p, unsigned v) {
    asm volatile("red.release.gpu.global.add.u32 [%0], %1;" :: "l"(p), "r"(v) : "memory");
}

// Grid barrier: CTA fence (bar.sync) + release-RED arrival + acquire-load
// poll on a counter that is zeroed by reset_kernel at the start of every
// launch. Only 1 thread per block polls.
__device__ __forceinline__ void gridbar(unsigned tgt) {
    __syncthreads();
    if (threadIdx.x == 0) {
        red_rel_add(&g_cnt, 1u);
        unsigned v;
        do { v = ld_acq(&g_cnt); } while ((int)(v - tgt) < 0);
    }
    __syncthreads();
}

__device__ __forceinline__ float softplus_f(float v) {
    return fmaxf(v, 0.f) + log1pf(expf(-fabsf(v)));
}

__device__ __forceinline__ float warp_sum(float a) {
#pragma unroll
    for (int o = 16; o > 0; o >>= 1) a += __shfl_xor_sync(0xffffffffu, a, o);
    return a;
}

__global__ void reset_kernel() { g_cnt = 0u; }

__global__ void __launch_bounds__(TPB, 1)
ode_kernel(const float* __restrict__ ts,  const float* __restrict__ W0,
           const float* __restrict__ b0,  const float* __restrict__ Wh,
           const float* __restrict__ bh,  const float* __restrict__ Wl,
           const float* __restrict__ bl,  const float* __restrict__ bW,
           const float* __restrict__ bb,  const float* __restrict__ hvec,
           const float* __restrict__ scale, const float* __restrict__ y0log,
           float* __restrict__ out)
{
    extern __shared__ float sm[];
    const int tid  = threadIdx.x;
    const int b    = blockIdx.x;
    const int warp = tid >> 5;
    const int lane = tid & 31;

    float* sWh = sm + OFF_WH;
    float* sWl = sm + OFF_WL;
    float* sz  = sm + OFF_Z;
    float* sx  = sm + OFF_X;
    float* sb0 = sm + OFF_B0;
    float* sbh = sm + OFF_BH;
    float* sbl = sm + OFF_BL;
    float* sbw = sm + OFF_BW;

    unsigned tgt = 0;   // barrier target; g_cnt was zeroed by reset_kernel

    // ---- W0 slice in registers: 2 rows per warp, 9 cols per lane ----
    float w0r[RPW][9];
#pragma unroll
    for (int j = 0; j < RPW; j++)
#pragma unroll
        for (int i = 0; i < 9; i++) {
            int col = lane + 32 * i;
            int row = b * RH + warp * RPW + j;
            w0r[j][i] = (warp < 8 && col < 273) ? __ldg(&W0[row * 273 + col]) : 0.f;
        }

    // ---- load weight slices into smem (once per launch) ----
    for (int idx = tid; idx < NHID * RH * WID; idx += TPB) {
        int l = idx >> 14;            // / (RH*WID) = /16384
        int rem = idx & 16383;
        int r = rem >> 10, k = rem & 1023;
        sWh[idx] = Wh[((l * WID) + (b * RH + r)) * WID + k];
    }
    for (int idx = tid; idx < RL * WID; idx += TPB) {
        int r = idx >> 10, k = idx & 1023;
        sWl[idx] = Wl[(b * RL + r) * WID + k];
    }
    if (tid < RH) sb0[tid] = b0[b * RH + tid];
    if (tid >= 32 && tid < 32 + NHID * RH) {
        int i = tid - 32; int l = i >> 4, r = i & 15;
        sbh[i] = bh[l * WID + b * RH + r];
    }
    if (tid >= 96 && tid < 96 + RL) sbl[tid - 96] = bl[b * RL + (tid - 96)];
    if (tid == 100) sm[OFF_BB] = bb[0];
    for (int idx = tid; idx < HID; idx += TPB) sbw[idx] = bW[idx];
    if (tid >= NY && tid < XPAD) sx[tid] = 0.f;   // zero-pad tail of x (stays 0)

    // ---- per-thread state registers (tid < NY): y, k1..k3 ----
    float y = 0.f, k1 = 0.f, k2 = 0.f, k3 = 0.f;
    if (tid < NY) {
        if (tid < NST) {
            float m = -1e30f;
            for (int i = 0; i < NST; i++) m = fmaxf(m, __ldg(&y0log[i]));
            float s = 0.f;
            for (int i = 0; i < NST; i++) s += expf(__ldg(&y0log[i]) - m);
            y = expf(__ldg(&y0log[tid]) - m) / s;
        } else {
            y = __ldg(&hvec[tid - NST]);
        }
    }
    __syncthreads();

    const float scl = scale[0];

    if (b == 0 && tid < NY) {                     // output row 0
        if (tid < NST) out[tid] = y;
        else           out[T_N * NST + (tid - NST)] = y;
    }

    for (int iv = 0; iv < T_N - 1; ++iv) {
        float dt  = (__ldg(&ts[iv + 1]) - __ldg(&ts[iv])) * (1.f / (float)SUB);
        float dt6 = dt * (1.f / 6.f);
        for (int ss = 0; ss < SUB; ++ss) {
            const int par = (iv * SUB + ss) & 1;
#pragma unroll
            for (int st = 0; st < 4; ++st) {
                // ---- x-build: read k[st-1] (visible since last barrier) ----
                if (tid < NY) {
                    float xv = y;
                    if (st > 0) {
                        float kp = __ldcg(&g_k[par][st - 1][tid]);
                        if (st == 1) k1 = kp; else if (st == 2) k2 = kp; else k3 = kp;
                        xv = fmaf((st == 3) ? dt : 0.5f * dt, kp, y);
                    }
                    sx[(tid < NST) ? (HID + tid) : (tid - NST)] = xv;
                }
                __syncthreads();

                if (warp < 8) {
                    // ---- layer 0: 273 -> 1024, 2 rows per warp ----
                    float a0 = 0.f, a1 = 0.f;
#pragma unroll
                    for (int i = 0; i < 9; i++) {
                        float xv = sx[lane + 32 * i];
                        a0 = fmaf(w0r[0][i], xv, a0);
                        a1 = fmaf(w0r[1][i], xv, a1);
                    }
                    a0 = warp_sum(a0);
                    a1 = warp_sum(a1);
                    if (lane == 0) {
                        int r = b * RH + warp * RPW;
                        __stcg(&g_z[0][r],     softplus_f(a0 + sb0[warp * RPW]));
                        __stcg(&g_z[0][r + 1], softplus_f(a1 + sb0[warp * RPW + 1]));
                    }
                } else if (b == 0) {
                    // ---- dedicated SEIR warp (block 0, warp 8) ----
                    float t = 0.f;
#pragma unroll
                    for (int i = 0; i < 8; i++) {
                        int k = lane + 32 * i;
                        t = fmaf(sbw[k], sx[k], t);
                    }
                    t = warp_sum(t);
                    if (lane == 0) {
                        float bb1 = 8.f / (1.f + expf(-(t + sm[OFF_BB]))) + 25.f;
                        const float MU   = (float)(0.041 / 12.0);
                        const float XI   = (float)(13.0 / 12.0);
                        const float XIMU = (float)(13.0 / 12.0 + 0.041 / 12.0);
                        const float MUSG = (float)(0.041 / 12.0 + 91.0 / 12.0);
                        const float SG   = (float)(91.0 / 12.0);
                        const float NU   = (float)(36.0 / 12.0);
                        const float NUMU = (float)(36.0 / 12.0 + 0.041 / 12.0);
                        const float MUGA = (float)(0.041 / 12.0 + 1.8 / 12.0);
                        const float GA   = (float)(1.8 / 12.0);
                        const float* s_ = &sx[HID];
                        float M  = s_[0],  S1 = s_[1],  E1 = s_[2],  E2 = s_[3];
                        float E3 = s_[4],  E4 = s_[5],  I1 = s_[6],  I2 = s_[7];
                        float I3 = s_[8],  I4 = s_[9],  R1 = s_[10], R2 = s_[11];
                        float R3 = s_[12], R4 = s_[13], S2 = s_[14], S3 = s_[15];
                        float S4 = s_[16];
                        float I = I1 + I2 + I3 + I4;
                        float R = R1 + R2 + R3 + R4;
                        float bb2 = 0.5f * bb1, bb3 = 0.35f * bb1, bb4 = 0.25f * bb1;
                        float d[NST];
                        d[0]  = R * MU - XIMU * M;
                        d[1]  = MU * (1.f - R) + XI * M - MU * S1 - bb1 * I * S1;
                        d[2]  = bb1 * I * S1 - MUSG * E1;
                        d[3]  = bb2 * I * S2 - MUSG * E2;
                        d[4]  = bb3 * I * S3 - MUSG * E3;
                        d[5]  = bb4 * I * S4 - MUSG * E4;
                        d[6]  = SG * E1 - NUMU * I1;
                        d[7]  = SG * E2 - NUMU * I2;
                        d[8]  = SG * E3 - NUMU * I3;
                        d[9]  = SG * E4 - NUMU * I4;
                        d[10] = NU * I1 - MUGA * R1;
                        d[11] = NU * I2 - MUGA * R2;
                        d[12] = NU * I3 - MUGA * R3;
                        d[13] = NU * I4 - MUGA * R4;
                        d[14] = GA * R1 - MU * S2 - bb2 * I * S2;
                        d[15] = GA * R2 - MU * S3 - bb3 * I * S3;
                        d[16] = GA * (R3 + R4) - MU * S4 - bb4 * I * S4;
#pragma unroll
                        for (int i2 = 0; i2 < NST; i2++)
                            __stcg(&g_k[par][st][i2], d[i2]);
                    }
                }
                tgt += NBLK; gridbar(tgt);

                // ---- 3 hidden layers: 1024 -> 1024, 2 rows per warp ----
#pragma unroll
                for (int l = 0; l < NHID; l++) {
                    int src = l & 1;           // 0,1,0 ; dst = src^1
                    if (tid < 256)
                        *(float4*)&sz[tid * 4] =
                            __ldcg((const float4*)&g_z[src][tid * 4]);
                    __syncthreads();
                    if (warp < 8) {
                        float a0 = 0.f, a1 = 0.f;
                        const float4* w40 =
                            (const float4*)&sWh[(l * RH + warp * RPW) * WID];
                        const float4* w41 = w40 + (WID / 4);
                        const float4* z4 = (const float4*)sz;
#pragma unroll
                        for (int i = 0; i < 8; i++) {
                            float4 z = z4[lane + 32 * i];
                            float4 a = w40[lane + 32 * i];
                            float4 c = w41[lane + 32 * i];
                            a0 = fmaf(a.x, z.x, a0); a0 = fmaf(a.y, z.y, a0);
                            a0 = fmaf(a.z, z.z, a0); a0 = fmaf(a.w, z.w, a0);
                            a1 = fmaf(c.x, z.x, a1); a1 = fmaf(c.y, z.y, a1);
                            a1 = fmaf(c.z, z.z, a1); a1 = fmaf(c.w, z.w, a1);
                        }
                        a0 = warp_sum(a0);
                        a1 = warp_sum(a1);
                        if (lane == 0) {
                            int r = b * RH + warp * RPW;
                            __stcg(&g_z[src ^ 1][r],
                                   softplus_f(a0 + sbh[l * RH + warp * RPW]));
                            __stcg(&g_z[src ^ 1][r + 1],
                                   softplus_f(a1 + sbh[l * RH + warp * RPW + 1]));
                        }
                    }
                    tgt += NBLK; gridbar(tgt);
                }

                // ---- final layer: 1024 -> 256, 1 row per warp (warps 0-3) ----
                if (tid < 256)
                    *(float4*)&sz[tid * 4] =
                        __ldcg((const float4*)&g_z[1][tid * 4]);
                __syncthreads();
                if (warp < RL) {
                    float acc = 0.f;
                    const float4* w4 = (const float4*)&sWl[warp * WID];
                    const float4* z4 = (const float4*)sz;
#pragma unroll
                    for (int i = 0; i < 8; i++) {
                        float4 a = w4[lane + 32 * i];
                        float4 z = z4[lane + 32 * i];
                        acc = fmaf(a.x, z.x, acc);
                        acc = fmaf(a.y, z.y, acc);
                        acc = fmaf(a.z, z.z, acc);
                        acc = fmaf(a.w, z.w, acc);
                    }
                    acc = warp_sum(acc);
                    if (lane == 0) {
                        float u = tanhf(0.01f * (acc + sbl[warp]));
                        __stcg(&g_k[par][st][NST + b * RL + warp], scl * u);
                    }
                }
                tgt += NBLK; gridbar(tgt);
            } // st

            // ---- RK4 combine (registers; k4 visible since last barrier) ----
            if (tid < NY) {
                float k4 = __ldcg(&g_k[par][3][tid]);
                y = fmaf(dt6, k1 + 2.f * (k2 + k3) + k4, y);
            }
        } // ss

        if (b == 0 && tid < NY) {
            if (tid < NST) out[(iv + 1) * NST + tid] = y;
            else           out[T_N * NST + (iv + 1) * HID + (tid - NST)] = y;
        }
    } // iv
}

extern "C" void kernel_launch(void* const* d_in, const int* in_sizes, int n_in,
                              void* d_out, int out_size) {
    (void)in_sizes; (void)n_in; (void)out_size;
    const float* ts    = (const float*)d_in[0];
    const float* W0    = (const float*)d_in[1];
    const float* b0    = (const float*)d_in[2];
    const float* Wh    = (const float*)d_in[3];
    const float* bh    = (const float*)d_in[4];
    const float* Wl    = (const float*)d_in[5];
    const float* bl    = (const float*)d_in[6];
    const float* bW    = (const float*)d_in[7];
    const float* bb    = (const float*)d_in[8];
    const float* hvec  = (const float*)d_in[9];
    const float* scale = (const float*)d_in[10];
    const float* y0log = (const float*)d_in[11];
    float* out = (float*)d_out;

    cudaFuncSetAttribute(ode_kernel,
                         cudaFuncAttributeMaxDynamicSharedMemorySize, SMEM_BYTES);
    reset_kernel<<<1, 1>>>();
    ode_kernel<<<NBLK, TPB, SMEM_BYTES>>>(ts, W0, b0, Wh, bh, Wl, bl, bW, bb,
                                          hvec, scale, y0log, out);
}

// round 9
// speedup vs baseline: 1.0281x; 1.0281x over previous
#include <cuda_runtime.h>

#define NBLK 128
#define TPB  288          // 9 warps: 8 MLP-row warps + 1 SEIR warp
#define WID  1024
#define HID  256
#define NST  17
#define NY   273          // 17 + 256
#define XPAD 288
#define RH   8            // hidden rows per block (1 per warp)
#define RL   2            // output rows per block (warps 0-1)
#define T_N  64
#define SUB  8
#define NHID 3

// ---------------- global scratch (no allocs allowed) ----------------
__device__ __align__(16) float g_z[2][WID];   // double-buffered layer activations
__device__ float g_k[2][4][NY];               // RK4 slopes, parity-buffered
__device__ unsigned g_cnt;                    // arrival counter (reset each launch)

// ---------------- shared memory layout (floats) ----------------
#define OFF_Z    0
#define OFF_X    (OFF_Z + WID)
#define OFF_B0   (OFF_X + XPAD)
#define OFF_BH   (OFF_B0 + RH)
#define OFF_BL   (OFF_BH + NHID*RH)
#define OFF_BB   (OFF_BL + RL)
#define OFF_BW   (OFF_BB + 1)
#define SMEM_FLOATS (OFF_BW + HID)
#define SMEM_BYTES  (SMEM_FLOATS * 4)      // ~6.4 KB

__device__ __forceinline__ unsigned ld_acq(unsigned* p) {
    unsigned v;
    asm volatile("ld.acquire.gpu.global.u32 %0, [%1];" : "=r"(v) : "l"(p) : "memory");
    return v;
}
__device__ __forceinline__ void red_rel_add(unsigned* p, unsigned v) {
    asm volatile("red.release.gpu.global.add.u32 [%0], %1;" :: "l"(p), "r"(v) : "memory");
}

// Grid barrier (PROVEN form, R4/R7): bar.sync + release-RED arrival +
// acquire-load poll. Every observation of the counter is an acquire —
// weak-poll variants measurably corrupt cross-die visibility on this HW.
__device__ __forceinline__ void gridbar(unsigned tgt) {
    __syncthreads();
    if (threadIdx.x == 0) {
        red_rel_add(&g_cnt, 1u);
        unsigned v;
        do { v = ld_acq(&g_cnt); } while ((int)(v - tgt) < 0);
    }
    __syncthreads();
}

__device__ __forceinline__ float softplus_f(float v) {
    return fmaxf(v, 0.f) + log1pf(expf(-fabsf(v)));
}

__device__ __forceinline__ float warp_sum(float a) {
#pragma unroll
    for (int o = 16; o > 0; o >>= 1) a += __shfl_xor_sync(0xffffffffu, a, o);
    return a;
}

__global__ void reset_kernel() { g_cnt = 0u; }

__global__ void __launch_bounds__(TPB, 1)
ode_kernel(const float* __restrict__ ts,  const float* __restrict__ W0,
           const float* __restrict__ b0,  const float* __restrict__ Wh,
           const float* __restrict__ bh,  const float* __restrict__ Wl,
           const float* __restrict__ bl,  const float* __restrict__ bW,
           const float* __restrict__ bb,  const float* __restrict__ hvec,
           const float* __restrict__ scale, const float* __restrict__ y0log,
           float* __restrict__ out)
{
    extern __shared__ float sm[];
    const int tid  = threadIdx.x;
    const int b    = blockIdx.x;
    const int warp = tid >> 5;
    const int lane = tid & 31;

    float* sz  = sm + OFF_Z;
    float* sx  = sm + OFF_X;
    float* sb0 = sm + OFF_B0;
    float* sbh = sm + OFF_BH;
    float* sbl = sm + OFF_BL;
    float* sbw = sm + OFF_BW;

    unsigned tgt = 0;   // barrier target; g_cnt was zeroed by reset_kernel

    // ---- ALL weights in registers ----
    // W0: 1 row per warp (row b*8+warp), 9 scalar cols per lane
    float w0r[9];
#pragma unroll
    for (int i = 0; i < 9; i++) {
        int col = lane + 32 * i;
        w0r[i] = (warp < 8 && col < 273)
                 ? __ldg(&W0[(b * RH + warp) * 273 + col]) : 0.f;
    }
    // Wh: 1 row per warp per layer, 8 float4 chunks per lane (cols lane*4+128i)
    float4 wh[NHID][8];
#pragma unroll
    for (int l = 0; l < NHID; l++)
#pragma unroll
        for (int i = 0; i < 8; i++)
            wh[l][i] = (warp < 8)
                ? __ldg((const float4*)&Wh[((l * WID) + (b * RH + warp)) * WID
                                           + lane * 4 + 128 * i])
                : make_float4(0.f, 0.f, 0.f, 0.f);
    // Wl: warps 0-1 own row b*2+warp
    float4 wl[8];
#pragma unroll
    for (int i = 0; i < 8; i++)
        wl[i] = (warp < RL)
            ? __ldg((const float4*)&Wl[(b * RL + warp) * WID + lane * 4 + 128 * i])
            : make_float4(0.f, 0.f, 0.f, 0.f);

    // ---- small constants into smem ----
    if (tid < RH) sb0[tid] = b0[b * RH + tid];
    if (tid >= 32 && tid < 32 + NHID * RH) {
        int i = tid - 32; int l = i >> 3, r = i & 7;
        sbh[i] = bh[l * WID + b * RH + r];
    }
    if (tid >= 64 && tid < 64 + RL) sbl[tid - 64] = bl[b * RL + (tid - 64)];
    if (tid == 66) sm[OFF_BB] = bb[0];
    for (int idx = tid; idx < HID; idx += TPB) sbw[idx] = bW[idx];
    if (tid >= NY && tid < XPAD) sx[tid] = 0.f;   // zero-pad tail of x (stays 0)

    // ---- per-thread state registers (tid < NY): y, k1..k3 ----
    float y = 0.f, k1 = 0.f, k2 = 0.f, k3 = 0.f;
    if (tid < NY) {
        if (tid < NST) {
            float m = -1e30f;
            for (int i = 0; i < NST; i++) m = fmaxf(m, __ldg(&y0log[i]));
            float s = 0.f;
            for (int i = 0; i < NST; i++) s += expf(__ldg(&y0log[i]) - m);
            y = expf(__ldg(&y0log[tid]) - m) / s;
        } else {
            y = __ldg(&hvec[tid - NST]);
        }
    }
    __syncthreads();

    const float scl = scale[0];

    if (b == 0 && tid < NY) {                     // output row 0
        if (tid < NST) out[tid] = y;
        else           out[T_N * NST + (tid - NST)] = y;
    }

    for (int iv = 0; iv < T_N - 1; ++iv) {
        float dt  = (__ldg(&ts[iv + 1]) - __ldg(&ts[iv])) * (1.f / (float)SUB);
        float dt6 = dt * (1.f / 6.f);
        for (int ss = 0; ss < SUB; ++ss) {
            const int par = (iv * SUB + ss) & 1;
#pragma unroll
            for (int st = 0; st < 4; ++st) {
                // ---- x-build: read k[st-1] (visible since last barrier) ----
                if (tid < NY) {
                    float xv = y;
                    if (st > 0) {
                        float kp = __ldcg(&g_k[par][st - 1][tid]);
                        if (st == 1) k1 = kp; else if (st == 2) k2 = kp; else k3 = kp;
                        xv = fmaf((st == 3) ? dt : 0.5f * dt, kp, y);
                    }
                    sx[(tid < NST) ? (HID + tid) : (tid - NST)] = xv;
                }
                __syncthreads();

                if (warp < 8) {
                    // ---- layer 0: 273 -> 1024, 1 row per warp, reg weights ----
                    float acc = 0.f;
#pragma unroll
                    for (int i = 0; i < 9; i++)
                        acc = fmaf(w0r[i], sx[lane + 32 * i], acc);
                    acc = warp_sum(acc);
                    if (lane == 0)
                        __stcg(&g_z[0][b * RH + warp], softplus_f(acc + sb0[warp]));
                } else if (b == 0) {
                    // ---- dedicated SEIR warp (block 0, warp 8) ----
                    float t = 0.f;
#pragma unroll
                    for (int i = 0; i < 8; i++) {
                        int k = lane + 32 * i;
                        t = fmaf(sbw[k], sx[k], t);
                    }
                    t = warp_sum(t);
                    if (lane == 0) {
                        float bb1 = 8.f / (1.f + expf(-(t + sm[OFF_BB]))) + 25.f;
                        const float MU   = (float)(0.041 / 12.0);
                        const float XI   = (float)(13.0 / 12.0);
                        const float XIMU = (float)(13.0 / 12.0 + 0.041 / 12.0);
                        const float MUSG = (float)(0.041 / 12.0 + 91.0 / 12.0);
                        const float SG   = (float)(91.0 / 12.0);
                        const float NU   = (float)(36.0 / 12.0);
                        const float NUMU = (float)(36.0 / 12.0 + 0.041 / 12.0);
                        const float MUGA = (float)(0.041 / 12.0 + 1.8 / 12.0);
                        const float GA   = (float)(1.8 / 12.0);
                        const float* s_ = &sx[HID];
                        float M  = s_[0],  S1 = s_[1],  E1 = s_[2],  E2 = s_[3];
                        float E3 = s_[4],  E4 = s_[5],  I1 = s_[6],  I2 = s_[7];
                        float I3 = s_[8],  I4 = s_[9],  R1 = s_[10], R2 = s_[11];
                        float R3 = s_[12], R4 = s_[13], S2 = s_[14], S3 = s_[15];
                        float S4 = s_[16];
                        float I = I1 + I2 + I3 + I4;
                        float R = R1 + R2 + R3 + R4;
                        float bb2 = 0.5f * bb1, bb3 = 0.35f * bb1, bb4 = 0.25f * bb1;
                        float d[NST];
                        d[0]  = R * MU - XIMU * M;
                        d[1]  = MU * (1.f - R) + XI * M - MU * S1 - bb1 * I * S1;
                        d[2]  = bb1 * I * S1 - MUSG * E1;
                        d[3]  = bb2 * I * S2 - MUSG * E2;
                        d[4]  = bb3 * I * S3 - MUSG * E3;
                        d[5]  = bb4 * I * S4 - MUSG * E4;
                        d[6]  = SG * E1 - NUMU * I1;
                        d[7]  = SG * E2 - NUMU * I2;
                        d[8]  = SG * E3 - NUMU * I3;
                        d[9]  = SG * E4 - NUMU * I4;
                        d[10] = NU * I1 - MUGA * R1;
                        d[11] = NU * I2 - MUGA * R2;
                        d[12] = NU * I3 - MUGA * R3;
                        d[13] = NU * I4 - MUGA * R4;
                        d[14] = GA * R1 - MU * S2 - bb2 * I * S2;
                        d[15] = GA * R2 - MU * S3 - bb3 * I * S3;
                        d[16] = GA * (R3 + R4) - MU * S4 - bb4 * I * S4;
#pragma unroll
                        for (int i2 = 0; i2 < NST; i2++)
                            __stcg(&g_k[par][st][i2], d[i2]);
                    }
                }
                tgt += NBLK; gridbar(tgt);

                // ---- 3 hidden layers: 1024 -> 1024, reg weights ----
#pragma unroll
                for (int l = 0; l < NHID; l++) {
                    int src = l & 1;           // 0,1,0 ; dst = src^1
                    if (tid < 256)
                        *(float4*)&sz[tid * 4] =
                            __ldcg((const float4*)&g_z[src][tid * 4]);
                    __syncthreads();
                    if (warp < 8) {
                        float acc = 0.f;
                        const float4* z4 = (const float4*)sz;
#pragma unroll
                        for (int i = 0; i < 8; i++) {
                            float4 z = z4[lane + 32 * i];
                            float4 a = wh[l][i];
                            acc = fmaf(a.x, z.x, acc);
                            acc = fmaf(a.y, z.y, acc);
                            acc = fmaf(a.z, z.z, acc);
                            acc = fmaf(a.w, z.w, acc);
                        }
                        acc = warp_sum(acc);
                        if (lane == 0)
                            __stcg(&g_z[src ^ 1][b * RH + warp],
                                   softplus_f(acc + sbh[l * RH + warp]));
                    }
                    tgt += NBLK; gridbar(tgt);
                }

                // ---- final layer: 1024 -> 256, warps 0-1, reg weights ----
                if (tid < 256)
                    *(float4*)&sz[tid * 4] =
                        __ldcg((const float4*)&g_z[1][tid * 4]);
                __syncthreads();
                if (warp < RL) {
                    float acc = 0.f;
                    const float4* z4 = (const float4*)sz;
#pragma unroll
                    for (int i = 0; i < 8; i++) {
                        float4 z = z4[lane + 32 * i];
                        float4 a = wl[i];
                        acc = fmaf(a.x, z.x, acc);
                        acc = fmaf(a.y, z.y, acc);
                        acc = fmaf(a.z, z.z, acc);
                        acc = fmaf(a.w, z.w, acc);
                    }
                    acc = warp_sum(acc);
                    if (lane == 0) {
                        float u = tanhf(0.01f * (acc + sbl[warp]));
                        __stcg(&g_k[par][st][NST + b * RL + warp], scl * u);
                    }
                }
                tgt += NBLK; gridbar(tgt);
            } // st

            // ---- RK4 combine (registers; k4 visible since last barrier) ----
            if (tid < NY) {
                float k4 = __ldcg(&g_k[par][3][tid]);
                y = fmaf(dt6, k1 + 2.f * (k2 + k3) + k4, y);
            }
        } // ss

        if (b == 0 && tid < NY) {
            if (tid < NST) out[(iv + 1) * NST + tid] = y;
            else           out[T_N * NST + (iv + 1) * HID + (tid - NST)] = y;
        }
    } // iv
}

extern "C" void kernel_launch(void* const* d_in, const int* in_sizes, int n_in,
                              void* d_out, int out_size) {
    (void)in_sizes; (void)n_in; (void)out_size;
    const float* ts    = (const float*)d_in[0];
    const float* W0    = (const float*)d_in[1];
    const float* b0    = (const float*)d_in[2];
    const float* Wh    = (const float*)d_in[3];
    const float* bh    = (const float*)d_in[4];
    const float* Wl    = (const float*)d_in[5];
    const float* bl    = (const float*)d_in[6];
    const float* bW    = (const float*)d_in[7];
    const float* bb    = (const float*)d_in[8];
    const float* hvec  = (const float*)d_in[9];
    const float* scale = (const float*)d_in[10];
    const float* y0log = (const float*)d_in[11];
    float* out = (float*)d_out;

    cudaFuncSetAttribute(ode_kernel,
                         cudaFuncAttributeMaxDynamicSharedMemorySize, SMEM_BYTES);
    reset_kernel<<<1, 1>>>();
    ode_kernel<<<NBLK, TPB, SMEM_BYTES>>>(ts, W0, b0, Wh, bh, Wl, bl, bW, bb,
                                          hvec, scale, y0log, out);
}